// round 12
// baseline (speedup 1.0000x reference)
#include <cuda_runtime.h>
#include <cuda_bf16.h>

// FuzzyLayer: out[b,s,d*I+i] = exp(-(x[b,s,i]-mu[d,i])^2 / sigma[d,i])
// B=16, S=2048, I=256, D=8.  256 MB write + 32 MB read -> HBM-write-bound.
//
// R11 -> R12: .wt regressed; .cs confirmed optimal. New structure test:
// remove the fill phase entirely. Thread owns (i4, row-slot) and computes
// ALL 8 'd' outputs from one x LDG.128 (x reuse in REGISTERS, not smem):
// 16 B loaded -> 512 B stored, with the next row's x prefetched before the
// 8-d store burst -> x latency hidden under the thread's own stores; no
// block-level store-silent fill window at all. Per-(d,i4) poly coeffs live
// in a 24 KB SoA smem table (conflict-free LDS), computed once; still
// exactly ONE barrier. Grid 1024 short blocks (desync), float4 traffic,
// __stcs streaming stores, __launch_bounds__(512,4).

static constexpr int BS    = 16 * 2048;    // 32768 rows
static constexpr int ROWS  = 32;           // rows per block
static constexpr int SLOTS = 8;            // row-slots (threads 512 = 8 x 64)
static constexpr int KITER = ROWS / SLOTS; // 4 rows per thread

__device__ __forceinline__ float ex2_approx(float t) {
    float r;
    asm("ex2.approx.ftz.f32 %0, %1;" : "=f"(r) : "f"(t));
    return r;
}

__global__ void __launch_bounds__(512, 4)
fuzzy_kernel(const float4* __restrict__ x4,
             const float4* __restrict__ fp4,
             float4* __restrict__ out4)
{
    // Coefficient tables, SoA: entry c4 = d*64+i4. exp2((a*x+b)*x+e).
    __shared__ float4 sa[512], sb[512], se[512];   // 24 KB

    const int tid  = threadIdx.x;
    const int i4   = tid & 63;               // float4 group within I
    const int slot = tid >> 6;               // row slot 0..7

    // Each thread builds the coeff entry for c4 = tid (same math as R4).
    {
        const int dd = tid >> 6, ii = tid & 63;
        const float4 p0 = fp4[dd * 128 + ii * 2];
        const float4 p1 = fp4[dd * 128 + ii * 2 + 1];
        const float L2E = 1.4426950408889634f;
        float4 a, b, e;
        a.x = -L2E / p0.y; b.x = -2.f * a.x * p0.x; e.x = a.x * p0.x * p0.x;
        a.y = -L2E / p0.w; b.y = -2.f * a.y * p0.z; e.y = a.y * p0.z * p0.z;
        a.z = -L2E / p1.y; b.z = -2.f * a.z * p1.x; e.z = a.z * p1.x * p1.x;
        a.w = -L2E / p1.w; b.w = -2.f * a.w * p1.z; e.w = a.w * p1.z * p1.z;
        sa[tid] = a; sb[tid] = b; se[tid] = e;
    }

    const int bs0 = blockIdx.x * ROWS;

    // Kick off the first x load before the barrier (overlaps coeff setup
    // of other warps).
    const float4* __restrict__ xin = x4 + (size_t)bs0 * 64 + slot * 64 + i4;
    float4 xcur = __ldg(xin);

    __syncthreads();                          // coeff table ready (ONE barrier)

    float4* __restrict__ oout = out4 + (size_t)bs0 * 512 + (size_t)slot * 512 + i4;

#pragma unroll
    for (int k = 0; k < KITER; ++k) {
        // Prefetch next row's x before the store burst.
        float4 xnext;
        if (k + 1 < KITER) xnext = __ldg(xin + (k + 1) * SLOTS * 64);

        float4* orow = oout + (size_t)k * SLOTS * 512;

#pragma unroll
        for (int d = 0; d < 8; ++d) {
            const int c = d * 64 + i4;        // conflict-free LDS (lane-consecutive)
            const float4 a = sa[c];
            const float4 b = sb[c];
            const float4 e = se[c];

            float4 o;
            o.x = ex2_approx(fmaf(fmaf(a.x, xcur.x, b.x), xcur.x, e.x));
            o.y = ex2_approx(fmaf(fmaf(a.y, xcur.y, b.y), xcur.y, e.y));
            o.z = ex2_approx(fmaf(fmaf(a.z, xcur.z, b.z), xcur.z, e.z));
            o.w = ex2_approx(fmaf(fmaf(a.w, xcur.w, b.w), xcur.w, e.w));

            __stcs(orow + d * 64, o);
        }
        xcur = xnext;
    }
}

extern "C" void kernel_launch(void* const* d_in, const int* in_sizes, int n_in,
                              void* d_out, int out_size)
{
    const float4* x4  = (const float4*)d_in[0];   // x: (16,2048,256) f32
    const float4* fp4 = (const float4*)d_in[1];   // fuzzy_params: (2048,2) f32
    float4* out4      = (float4*)d_out;           // (16,2048,2048) f32

    fuzzy_kernel<<<BS / ROWS, 512>>>(x4, fp4, out4);   // 1024 blocks
}

// round 13
// speedup vs baseline: 2.3079x; 2.3079x over previous
#include <cuda_runtime.h>
#include <cuda_bf16.h>

// FuzzyLayer: out[b,s,d*I+i] = exp(-(x[b,s,i]-mu[d,i])^2 / sigma[d,i])
// B=16, S=2048, I=256, D=8.  256 MB write + 32 MB read -> HBM-write-bound.
//
// FINAL (R13): exact R4 champion structure (45.5us, best of 12 rounds).
// Every alternative axis tested and rejected: occupancy push (R3), smaller
// tiles (R8), persistent blocks (R5), chunked pipelines (R6), TMA bulk
// stores (R7), cp.async fill (R9), default/.wt store policy (R10/R11),
// register-reuse restructure (R12, 2.5x regression from smem coeff traffic).
// Single micro-tweak vs R4: fill LDGs issue BEFORE param LDGs so the
// barrier-critical x loads enter the memory system first.
//
// Structure: 1024 short blocks (cross-CTA desync keeps DRAM fed during
// fills), 32-row x tile staged via one cooperative LDG->STS fill + ONE
// barrier, thread owns a fixed output column group with poly coeffs in
// registers (exp2((a*x+b)*x+e), 2 FFMA + 1 MUFU per element), all 8 'd'
// groups co-resident per CTA, float4 traffic, __stcs streaming stores
// (proven optimal: default pays cross-replay writeback tax, .wt pays
// in-kernel drain tax), __launch_bounds__(512,4).
// Achieved: 288 MB logical / 45.5us = 6.3 TB/s (~79% of HBM spec).

static constexpr int BS   = 16 * 2048;     // 32768 rows
static constexpr int ROWS = 32;            // rows per block (32 KB smem)

__device__ __forceinline__ float ex2_approx(float t) {
    float r;
    asm("ex2.approx.ftz.f32 %0, %1;" : "=f"(r) : "f"(t));
    return r;
}

__global__ void __launch_bounds__(512, 4)
fuzzy_kernel(const float4* __restrict__ x4,
             const float4* __restrict__ fp4,
             float4* __restrict__ out4)
{
    __shared__ float4 sx[ROWS * 64];         // 32 KB: ROWS rows of x (256 f32)

    const int tid = threadIdx.x;
    const int i4  = tid & 63;                // float4 group within I
    const int d   = tid >> 6;                // fuzzy degree

    const int bs0 = blockIdx.x * ROWS;

    // Fill loads first: 2048 float4 / 512 threads = 4 per thread (MLP=4).
    const float4* __restrict__ src = x4 + (size_t)bs0 * 64;
    float4 v0 = src[tid];
    float4 v1 = src[tid + 512];
    float4 v2 = src[tid + 1024];
    float4 v3 = src[tid + 1536];

    // Param loads + coefficient setup overlap the fill loads' latency.
    // fuzzy_params (2048,2) row-major: fp[2j]=mu_j, fp[2j+1]=sigma_j, j=d*256+i.
    const float4 p0 = fp4[d * 128 + i4 * 2];
    const float4 p1 = fp4[d * 128 + i4 * 2 + 1];

    const float L2E = 1.4426950408889634f;
    // exponent(x) = rs*(x-mu)^2 = (a*x + b)*x + e
    const float a0 = -L2E / p0.y, b0 = -2.f * a0 * p0.x, e0 = a0 * p0.x * p0.x;
    const float a1 = -L2E / p0.w, b1 = -2.f * a1 * p0.z, e1 = a1 * p0.z * p0.z;
    const float a2 = -L2E / p1.y, b2 = -2.f * a2 * p1.x, e2 = a2 * p1.x * p1.x;
    const float a3 = -L2E / p1.w, b3 = -2.f * a3 * p1.z, e3 = a3 * p1.z * p1.z;

    sx[tid]        = v0;
    sx[tid + 512]  = v1;
    sx[tid + 1024] = v2;
    sx[tid + 1536] = v3;
    __syncthreads();

    float4* __restrict__ oout = out4 + (size_t)bs0 * 512 + tid;

#pragma unroll 4
    for (int r = 0; r < ROWS; ++r) {
        const float4 xv = sx[r * 64 + i4];

        float4 o;
        o.x = ex2_approx(fmaf(fmaf(a0, xv.x, b0), xv.x, e0));
        o.y = ex2_approx(fmaf(fmaf(a1, xv.y, b1), xv.y, e1));
        o.z = ex2_approx(fmaf(fmaf(a2, xv.z, b2), xv.z, e2));
        o.w = ex2_approx(fmaf(fmaf(a3, xv.w, b3), xv.w, e3));

        __stcs(oout + r * 512, o);
    }
}

extern "C" void kernel_launch(void* const* d_in, const int* in_sizes, int n_in,
                              void* d_out, int out_size)
{
    const float4* x4  = (const float4*)d_in[0];   // x: (16,2048,256) f32
    const float4* fp4 = (const float4*)d_in[1];   // fuzzy_params: (2048,2) f32
    float4* out4      = (float4*)d_out;           // (16,2048,2048) f32

    fuzzy_kernel<<<BS / ROWS, 512>>>(x4, fp4, out4);   // 1024 blocks
}

// round 14
// speedup vs baseline: 2.5527x; 1.1061x over previous
#include <cuda_runtime.h>
#include <cuda_bf16.h>

// FuzzyLayer: out[b,s,d*I+i] = exp(-(x[b,s,i]-mu[d,i])^2 / sigma[d,i])
// B=16, S=2048, I=256, D=8.  256 MB write + 32 MB read -> HBM-write-bound.
//
// FINAL: exact R4 champion (45.5us best of 13 rounds; 6.3 TB/s logical,
// ~79% of HBM spec on an 8:1 write-dominated stream).
// Axes tested and rejected: occupancy push (R3: +occ, -perf), persistent
// single-wave (R5), chunked cp.async pipeline (R6), TMA bulk stores (R7),
// smaller tiles (R8), cp.async fill (R9), default/.wt store policy
// (R10/R11: .cs optimal — default pays cross-replay L2-writeback tax, .wt
// pays in-kernel drain tax), register-reuse restructure (R12: smem coeff
// traffic 2.5x regression), prologue reordering (R13: param-loads-first +
// interleaved LDG/STS fill is the right order; do not touch).
//
// Structure: 1024 short blocks (cross-CTA desync keeps DRAM fed during
// fills), 32-row x tile staged via one cooperative fill + ONE barrier,
// thread owns a fixed output column group with poly coeffs in registers
// (exp2((a*x+b)*x+e), 2 FFMA + 1 MUFU per element), all 8 'd' groups
// co-resident per CTA, float4 traffic, __stcs streaming stores,
// __launch_bounds__(512,4).

static constexpr int BATCH = 16;
static constexpr int SEQ   = 2048;
static constexpr int BS    = BATCH * SEQ;   // 32768 rows
static constexpr int ROWS  = 32;            // rows per block (32 KB smem)

__device__ __forceinline__ float ex2_approx(float t) {
    float r;
    asm("ex2.approx.ftz.f32 %0, %1;" : "=f"(r) : "f"(t));
    return r;
}

__global__ void __launch_bounds__(512, 4)
fuzzy_kernel(const float4* __restrict__ x4,
             const float4* __restrict__ fp4,
             float4* __restrict__ out4)
{
    __shared__ float4 sx[ROWS * 64];         // 32 KB: ROWS rows of x (256 f32)

    const int tid = threadIdx.x;
    const int c4  = tid;                      // output float4 column group
    const int i4  = c4 & 63;                  // float4 group within I
    const int d   = c4 >> 6;                  // fuzzy degree

    // fuzzy_params (2048,2) row-major: fp[2j]=mu_j, fp[2j+1]=sigma_j, j=d*256+i.
    const float4 p0 = fp4[d * 128 + i4 * 2];
    const float4 p1 = fp4[d * 128 + i4 * 2 + 1];

    const float L2E = 1.4426950408889634f;
    // exponent(x) = rs*(x-mu)^2 = (a*x + b)*x + e
    const float a0 = -L2E / p0.y, b0 = -2.f * a0 * p0.x, e0 = a0 * p0.x * p0.x;
    const float a1 = -L2E / p0.w, b1 = -2.f * a1 * p0.z, e1 = a1 * p0.z * p0.z;
    const float a2 = -L2E / p1.y, b2 = -2.f * a2 * p1.x, e2 = a2 * p1.x * p1.x;
    const float a3 = -L2E / p1.w, b3 = -2.f * a3 * p1.z, e3 = a3 * p1.z * p1.z;

    const int bs0 = blockIdx.x * ROWS;

    // Cooperative fill: 2048 float4 / 512 threads = 4 per thread (MLP=4).
    const float4* __restrict__ src = x4 + bs0 * 64;
#pragma unroll
    for (int k = 0; k < ROWS * 64 / 512; ++k)
        sx[tid + k * 512] = src[tid + k * 512];
    __syncthreads();

    float4* __restrict__ oout = out4 + bs0 * 512 + c4;

#pragma unroll 4
    for (int r = 0; r < ROWS; ++r) {
        const float4 xv = sx[r * 64 + i4];

        float4 o;
        o.x = ex2_approx(fmaf(fmaf(a0, xv.x, b0), xv.x, e0));
        o.y = ex2_approx(fmaf(fmaf(a1, xv.y, b1), xv.y, e1));
        o.z = ex2_approx(fmaf(fmaf(a2, xv.z, b2), xv.z, e2));
        o.w = ex2_approx(fmaf(fmaf(a3, xv.w, b3), xv.w, e3));

        __stcs(oout + r * 512, o);
    }
}

extern "C" void kernel_launch(void* const* d_in, const int* in_sizes, int n_in,
                              void* d_out, int out_size)
{
    const float4* x4  = (const float4*)d_in[0];   // x: (16,2048,256) f32
    const float4* fp4 = (const float4*)d_in[1];   // fuzzy_params: (2048,2) f32
    float4* out4      = (float4*)d_out;           // (16,2048,2048) f32

    fuzzy_kernel<<<BS / ROWS, 512>>>(x4, fp4, out4);   // 1024 blocks
}